// round 17
// baseline (speedup 1.0000x reference)
#include <cuda_runtime.h>
#include <cuda_bf16.h>
#include <mma.h>
#include <math.h>
#include <stdint.h>
using namespace nvcuda;

typedef unsigned int u32; typedef unsigned long long ull;
#define NB 65536
#define RPC 128
#define NCTA 512
#define THREADS 256

// ---- device scratch: pre-split bf16 weight images --------------------------
__device__ __align__(16) __nv_bfloat16 g_W1[2][1024*128];   // We0 [h,l][k*128+n]
__device__ __align__(16) __nv_bfloat16 g_Wc[6][2][128*128]; // e1,e2,c0,c1,a0,a1; [h,l]
__device__ float g_part[NCTA];
__device__ u32   g_ctr = 0;

// ---- smem map (bytes) ------------------------------------------------------
#define LDX 40
#define SX     0                       // X splits h,l: 128*40*2 B each (20480)
#define SW     35840                   // W stage: 2 x [32][136]*2B = 8704 each
#define SACT_A 76288                   // Ah,Al bf16 [128][136] (69632); mode2 f32 scratch
#define SACT_B 145920                  // chain pong (69632); during GEMM1/VQ:
#define SXF    SACT_B                  //   fp32 X chunk [128][36]   = 18432
#define SWP    (SACT_B+18432)         //   fp32 Wp chunk [32][68]   = 8704
#define SXQ2   (SACT_B+27136)         //   xqs f32 [128][68]        = 34816
#define SSCR   215552                  // 8 x 1KB warp tile scratch
#define SAUX   223744                  // rowpart / bias cache
#define SMISC  224768                  // flag + wsum[8]
#define SMEM_TOTAL 224832

extern __shared__ unsigned char smem[];

// ---- exact fp32x2 helpers --------------------------------------------------
__device__ __forceinline__ ull pk2(float a,float b){ ull r; asm("mov.b64 %0,{%1,%2};":"=l"(r):"f"(a),"f"(b)); return r; }
__device__ __forceinline__ void ffma2(ull&d,ull a,ull b){ asm("fma.rn.f32x2 %0,%1,%2,%3;":"=l"(d):"l"(a),"l"(b),"l"(d)); }
__device__ __forceinline__ float2 up2(ull v){ float2 f; asm("mov.b64 {%0,%1},%2;":"=f"(f.x),"=f"(f.y):"l"(v)); return f; }

typedef wmma::fragment<wmma::matrix_a,16,16,16,__nv_bfloat16,wmma::row_major> FragA;
typedef wmma::fragment<wmma::matrix_b,16,16,16,__nv_bfloat16,wmma::row_major> FragB;
typedef wmma::fragment<wmma::accumulator,16,16,16,float> FragC;

// ---- prep: split weights ---------------------------------------------------
__global__ void prep_kernel(const float* We0,const float* We1,const float* We2,
                            const float* Wc0,const float* Wc1,const float* Wa0,const float* Wa1)
{
    int id = blockIdx.x*256 + threadIdx.x;
    if (id < 1024*128){
        float f = We0[id];
        __nv_bfloat16 h = __float2bfloat16_rn(f);
        g_W1[0][id]=h; g_W1[1][id]=__float2bfloat16_rn(f - __bfloat162float(h));
    } else {
        id -= 1024*128;
        if (id >= 6*16384) return;
        int g = id/16384, e = id%16384;
        const float* W = g==0?We1 : g==1?We2 : g==2?Wc0 : g==3?Wc1 : g==4?Wa0 : Wa1;
        float f = W[e];
        __nv_bfloat16 h = __float2bfloat16_rn(f);
        g_Wc[g][0][e]=h; g_Wc[g][1][e]=__float2bfloat16_rn(f - __bfloat162float(h));
    }
}

// ---- chain GEMM (128x128 @ 128x128, 2-way split, 3 terms) ------------------
__device__ void chain_gemm(int g, u32 aoff, int mode, u32 doff,
                           const float* bias, const float* Wc2, const float* bc2,
                           float* gout, int tid, int row0)
{
    const int w = tid>>5, lane = tid&31, rgw = w>>1, cgw = w&1;
    FragC acc[2][4];
#pragma unroll
    for (int rt=0; rt<2; ++rt)
#pragma unroll
        for (int ct=0; ct<4; ++ct) wmma::fill_fragment(acc[rt][ct], 0.f);

    for (int kc=0; kc<4; ++kc){
#pragma unroll
        for (int s=0; s<2; ++s)
#pragma unroll
            for (int t=0; t<2; ++t){
                int i = tid + t*256;
                int kk = i>>4, q = i&15;
                float4 v = ((const float4*)(&g_Wc[g][s][0]))[(kc*32+kk)*16 + q];
                ((float4*)(smem+SW+s*8704))[kk*17 + q] = v;
            }
        __syncthreads();
        const __nv_bfloat16* Ah = (const __nv_bfloat16*)(smem+aoff);
        const __nv_bfloat16* Al = Ah + 17408;
        const __nv_bfloat16* Wh = (const __nv_bfloat16*)(smem+SW);
        const __nv_bfloat16* Wl = Wh + 4352;
#pragma unroll
        for (int kt=0; kt<2; ++kt){
            FragA aH[2], aL[2];
#pragma unroll
            for (int rt=0; rt<2; ++rt){
                const __nv_bfloat16* ap = Ah + (rgw*32+rt*16)*136 + kc*32 + kt*16;
                wmma::load_matrix_sync(aH[rt], ap, 136);
                wmma::load_matrix_sync(aL[rt], Al + (ap-Ah), 136);
            }
#pragma unroll
            for (int ct=0; ct<4; ++ct){
                int gc = cgw*64 + ct*16;
                FragB bH, bL;
                wmma::load_matrix_sync(bH, Wh + kt*16*136 + gc, 136);
                wmma::load_matrix_sync(bL, Wl + kt*16*136 + gc, 136);
#pragma unroll
                for (int rt=0; rt<2; ++rt){
                    wmma::mma_sync(acc[rt][ct], aH[rt], bH, acc[rt][ct]);
                    wmma::mma_sync(acc[rt][ct], aH[rt], bL, acc[rt][ct]);
                    wmma::mma_sync(acc[rt][ct], aL[rt], bH, acc[rt][ct]);
                }
            }
        }
        __syncthreads();
    }
    float* ws = (float*)(smem+SSCR) + w*256;
    if (mode == 0){
        __nv_bfloat16* Ch = (__nv_bfloat16*)(smem+doff);
        __nv_bfloat16* Cl = Ch + 17408;
#pragma unroll
        for (int rt=0; rt<2; ++rt)
#pragma unroll
            for (int ct=0; ct<4; ++ct){
                wmma::store_matrix_sync(ws, acc[rt][ct], 16, wmma::mem_row_major);
                __syncwarp();
                int rb = rgw*32+rt*16, gcb = cgw*64+ct*16;
#pragma unroll
                for (int e=0; e<8; ++e){
                    int idx = lane*8+e, r = idx>>4, c = idx&15, gc = gcb+c;
                    float v = fmaxf(ws[idx] + bias[gc], 0.f);
                    __nv_bfloat16 h = __float2bfloat16_rn(v);
                    Ch[(rb+r)*136+gc] = h;
                    Cl[(rb+r)*136+gc] = __float2bfloat16_rn(v - __bfloat162float(h));
                }
                __syncwarp();
            }
        __syncthreads();
    } else if (mode == 1){
        float* rowpart = (float*)(smem+SAUX);
        float pr[2] = {0.f, 0.f};
#pragma unroll
        for (int rt=0; rt<2; ++rt)
#pragma unroll
            for (int ct=0; ct<4; ++ct){
                wmma::store_matrix_sync(ws, acc[rt][ct], 16, wmma::mem_row_major);
                __syncwarp();
                int gcb = cgw*64+ct*16;
#pragma unroll
                for (int e=0; e<8; ++e){
                    int idx = lane*8+e, gc = gcb + (idx&15);
                    float v = fmaxf(ws[idx] + bias[gc], 0.f);
                    pr[rt] = fmaf(v, Wc2[gc], pr[rt]);
                }
                __syncwarp();
            }
#pragma unroll
        for (int rt=0; rt<2; ++rt){
            float s = pr[rt] + __shfl_xor_sync(0xffffffffu, pr[rt], 1);
            if (!(lane&1))
                rowpart[(rgw*32+rt*16+(lane>>1))*2 + cgw] = s;
        }
        __syncthreads();
        if (tid < 128)
            gout[row0+tid] = rowpart[tid*2] + rowpart[tid*2+1] + bc2[0];
        __syncthreads();
    } else {
        float* scr = (float*)(smem+SACT_A);
#pragma unroll
        for (int rt=0; rt<2; ++rt)
#pragma unroll
            for (int ct=0; ct<4; ++ct)
                wmma::store_matrix_sync(scr + (rgw*32+rt*16)*132 + cgw*64+ct*16,
                                        acc[rt][ct], 132, wmma::mem_row_major);
        float* bs = (float*)(smem+SAUX);
        if (tid < 128) bs[tid] = bias[tid];
        __syncthreads();
        if (tid < 128){
            float* rowp = scr + tid*132;
            float m = -3.402823e38f;
            for (int c=0; c<128; ++c) m = fmaxf(m, rowp[c]+bs[c]);
            float s = 0.f;
            for (int c=0; c<128; ++c){ float e = expf(rowp[c]+bs[c]-m); rowp[c]=e; s+=e; }
            float inv = 1.f/s;
            for (int c=0; c<32; ++c){
                float4 v = *(float4*)(rowp + c*4);
                v.x*=inv; v.y*=inv; v.z*=inv; v.w*=inv;
                *(float4*)(gout + (size_t)(row0+tid)*128 + c*4) = v;
            }
        }
        __syncthreads();
    }
}

// ---- main kernel ------------------------------------------------------------
__global__ void __launch_bounds__(THREADS,1)
acsq_kernel(const float* __restrict__ x,   const float* __restrict__ W_p,
            const float* __restrict__ b_e0, const float* __restrict__ b_e1,
            const float* __restrict__ b_e2, const float* __restrict__ b_p,
            const float* __restrict__ E,
            const float* __restrict__ b_a0, const float* __restrict__ b_a1,
            const float* __restrict__ b_c0, const float* __restrict__ b_c1,
            const float* __restrict__ W_c2, const float* __restrict__ b_c2,
            float* __restrict__ out_probs, float* __restrict__ out_critic,
            float* __restrict__ out_vq,    float* __restrict__ out_idx)
{
    const int tid = threadIdx.x, row0 = blockIdx.x*RPC;
    const int w = tid>>5, lane = tid&31, rgw = w>>1, cgw = w&1;
    float* misc = (float*)(smem+SMISC);

    // ===== GEMM1: emb = relu(X@We0+b) via HMMA 3-term; xq = X@Wp exact fp32x2
    {
        FragC acc[2][4];
#pragma unroll
        for (int rt=0; rt<2; ++rt)
#pragma unroll
            for (int ct=0; ct<4; ++ct) wmma::fill_fragment(acc[rt][ct], 0.f);
        const int ty = tid>>4, tx = tid&15;      // fp32 xq tile: 8 rows x 4 cols
        ull xacc[8][2];
#pragma unroll
        for (int i=0;i<8;++i){ xacc[i][0]=0ULL; xacc[i][1]=0ULL; }

        for (int kc=0; kc<32; ++kc){
            // X chunk: fp32 copy + bf16 h/l splits
#pragma unroll
            for (int t=0; t<8; ++t){
                int i = tid + t*256;
                int r = i>>4, c2 = i&15;
                float2 v = *(const float2*)(x + (size_t)(row0+r)*1024 + kc*32 + 2*c2);
                ((float2*)(smem+SXF))[r*18 + c2] = v;
                __nv_bfloat16 h0=__float2bfloat16_rn(v.x);
                __nv_bfloat16 l0=__float2bfloat16_rn(v.x-__bfloat162float(h0));
                __nv_bfloat16 h1=__float2bfloat16_rn(v.y);
                __nv_bfloat16 l1=__float2bfloat16_rn(v.y-__bfloat162float(h1));
                u32 off = (u32)(r*LDX + 2*c2)*2;
                *(u32*)(smem+SX+off)       = ((u32)__bfloat16_as_ushort(h1)<<16)|__bfloat16_as_ushort(h0);
                *(u32*)(smem+SX+10240+off) = ((u32)__bfloat16_as_ushort(l1)<<16)|__bfloat16_as_ushort(l0);
            }
            // We0 h/l chunk [32][128] -> [32][136]
#pragma unroll
            for (int s=0; s<2; ++s)
#pragma unroll
                for (int t=0; t<2; ++t){
                    int i = tid + t*256;
                    int kk = i>>4, q = i&15;
                    float4 v = ((const float4*)(&g_W1[s][0]))[(kc*32+kk)*16 + q];
                    ((float4*)(smem+SW+s*8704))[kk*17 + q] = v;
                }
            // Wp fp32 chunk [32][64] -> [32][68]
#pragma unroll
            for (int t=0; t<2; ++t){
                int i = tid + t*256;
                int kk = i>>4, q = i&15;
                float4 v = *((const float4*)(W_p + (size_t)(kc*32+kk)*64 + q*4));
                *((float4*)((float*)(smem+SWP) + kk*68 + q*4)) = v;
            }
            __syncthreads();
            // tensor: emb columns
            const __nv_bfloat16* Xh = (const __nv_bfloat16*)(smem+SX);
            const __nv_bfloat16* Xl = Xh + 5120;
            const __nv_bfloat16* Wh = (const __nv_bfloat16*)(smem+SW);
            const __nv_bfloat16* Wl = Wh + 4352;
#pragma unroll
            for (int kt=0; kt<2; ++kt){
                FragA aH[2], aL[2];
#pragma unroll
                for (int rt=0; rt<2; ++rt){
                    const __nv_bfloat16* xp = Xh + (rgw*32+rt*16)*LDX + kt*16;
                    wmma::load_matrix_sync(aH[rt], xp, LDX);
                    wmma::load_matrix_sync(aL[rt], Xl + (xp-Xh), LDX);
                }
#pragma unroll
                for (int ct=0; ct<4; ++ct){
                    int gc = cgw*64 + ct*16;
                    FragB bH, bL;
                    wmma::load_matrix_sync(bH, Wh + kt*16*136 + gc, 136);
                    wmma::load_matrix_sync(bL, Wl + kt*16*136 + gc, 136);
#pragma unroll
                    for (int rt=0; rt<2; ++rt){
                        wmma::mma_sync(acc[rt][ct], aH[rt], bH, acc[rt][ct]);
                        wmma::mma_sync(acc[rt][ct], aH[rt], bL, acc[rt][ct]);
                        wmma::mma_sync(acc[rt][ct], aL[rt], bH, acc[rt][ct]);
                    }
                }
            }
            // fp32x2: xq columns (ascending k -> bitwise-exact vs proven kernels)
            {
                const float* Xf = (const float*)(smem+SXF);
                const float* Wp = (const float*)(smem+SWP);
#pragma unroll
                for (int k4=0; k4<8; ++k4){
                    float4 a4[8];
#pragma unroll
                    for (int i=0;i<8;++i)
                        a4[i] = *((const float4*)(Xf + (ty*8+i)*36 + k4*4));
#pragma unroll
                    for (int kin=0; kin<4; ++kin){
                        int k = k4*4+kin;
                        ulonglong2 bq = *((const ulonglong2*)(Wp + k*68 + tx*4));
                        ull b0 = bq.x, b1 = bq.y;
#pragma unroll
                        for (int i=0;i<8;++i){
                            float a = ((const float*)&a4[i])[kin];
                            ull pa = pk2(a,a);
                            ffma2(xacc[i][0], pa, b0);
                            ffma2(xacc[i][1], pa, b1);
                        }
                    }
                }
            }
            __syncthreads();
        }
        // emb epilogue -> SACT_A split pair
        float* ws = (float*)(smem+SSCR) + w*256;
        __nv_bfloat16* Ch = (__nv_bfloat16*)(smem+SACT_A);
        __nv_bfloat16* Cl = Ch + 17408;
#pragma unroll
        for (int rt=0; rt<2; ++rt)
#pragma unroll
            for (int ct=0; ct<4; ++ct){
                wmma::store_matrix_sync(ws, acc[rt][ct], 16, wmma::mem_row_major);
                __syncwarp();
                int rb = rgw*32+rt*16, gcb = cgw*64+ct*16;
#pragma unroll
                for (int e=0; e<8; ++e){
                    int idx = lane*8+e, r = idx>>4, c = idx&15, gc = gcb+c;
                    float v = fmaxf(ws[idx] + b_e0[gc], 0.f);
                    __nv_bfloat16 h = __float2bfloat16_rn(v);
                    Ch[(rb+r)*136+gc] = h;
                    Cl[(rb+r)*136+gc] = __float2bfloat16_rn(v - __bfloat162float(h));
                }
                __syncwarp();
            }
        // xq epilogue -> xqs fp32
        float* xqs = (float*)(smem+SXQ2);
#pragma unroll
        for (int i=0;i<8;++i)
#pragma unroll
            for (int j=0;j<2;++j){
                float2 v = up2(xacc[i][j]);
                int c = tx*4 + 2*j;
                xqs[(ty*8+i)*68 + c]     = v.x + b_p[c];
                xqs[(ty*8+i)*68 + c + 1] = v.y + b_p[c+1];
            }
        __syncthreads();
    }

    // ===== VQ: exact fp32x2 argmin + e_latent partials =======================
    {
        float* xqs   = (float*)(smem+SXQ2);
        float* EsT   = (float*)(smem+SW);      // [64][68]
        float* Enorm = EsT + 64*68;
        const int cg = tid&7, rgv = tid>>3, r0 = rgv*4;
        float best[4]; int bidx[4];
#pragma unroll
        for (int i=0;i<4;++i){ best[i]=3.402823e38f; bidx[i]=0; }
        for (int cc=0; cc<8; ++cc){
#pragma unroll
            for (int t=0; t<4; ++t){
                int idx = tid + t*256, dq = idx>>6, c = idx&63;
                float4 v = *((const float4*)(E + (size_t)(cc*64+c)*64 + dq*4));
                EsT[(dq*4+0)*68+c]=v.x; EsT[(dq*4+1)*68+c]=v.y;
                EsT[(dq*4+2)*68+c]=v.z; EsT[(dq*4+3)*68+c]=v.w;
            }
            __syncthreads();
            if (tid<64){
                float s=0.f;
#pragma unroll 8
                for (int d=0; d<64; ++d){ float e=EsT[d*68+tid]; s=fmaf(e,e,s); }
                Enorm[tid]=s;
            }
            __syncthreads();
            ull acc2[4][4];
#pragma unroll
            for (int i=0;i<4;++i)
#pragma unroll
                for (int j=0;j<4;++j) acc2[i][j]=0ULL;
#pragma unroll
            for (int d4=0; d4<16; ++d4){
                float4 a4[4];
#pragma unroll
                for (int i=0;i<4;++i)
                    a4[i] = *((const float4*)(xqs + (r0+i)*68 + d4*4));
#pragma unroll
                for (int din=0; din<4; ++din){
                    ull pa[4];
#pragma unroll
                    for (int i=0;i<4;++i){
                        float a = ((const float*)&a4[i])[din]; pa[i]=pk2(a,a);
                    }
                    const ulonglong2* bp = (const ulonglong2*)(EsT + (d4*4+din)*68 + cg*8);
                    ulonglong2 b01=bp[0], b23=bp[1];
                    ull b[4]={b01.x,b01.y,b23.x,b23.y};
#pragma unroll
                    for (int i=0;i<4;++i)
#pragma unroll
                        for (int j=0;j<4;++j) ffma2(acc2[i][j], pa[i], b[j]);
                }
            }
#pragma unroll
            for (int j=0;j<4;++j){
                int c0 = cg*8+2*j, g0 = cc*64+c0;
                float n0=Enorm[c0], n1=Enorm[c0+1];
#pragma unroll
                for (int i=0;i<4;++i){
                    float2 dv = up2(acc2[i][j]); float s;
                    s=fmaf(-2.f,dv.x,n0); if(s<best[i]){best[i]=s;bidx[i]=g0;}
                    s=fmaf(-2.f,dv.y,n1); if(s<best[i]){best[i]=s;bidx[i]=g0+1;}
                }
            }
            __syncthreads();
        }
#pragma unroll
        for (int i=0;i<4;++i){
            float v=best[i]; int bi=bidx[i];
#pragma unroll
            for (int o=1;o<=4;o<<=1){
                float ov=__shfl_xor_sync(0xffffffffu,v,o);
                int   oi=__shfl_xor_sync(0xffffffffu,bi,o);
                if (ov<v || (ov==v && oi<bi)){ v=ov; bi=oi; }
            }
            best[i]=v; bidx[i]=bi;
        }
        float s_lat = 0.f;
        if (cg==0){
#pragma unroll
            for (int i=0;i<4;++i){
                int r=r0+i;
                out_idx[row0+r]=(float)bidx[i];
                const float* e = E + (size_t)bidx[i]*64;
                float s=0.f;
#pragma unroll 8
                for (int d=0; d<64; ++d){ float df=e[d]-xqs[r*68+d]; s=fmaf(df,df,s); }
                s_lat += s;
            }
        }
#pragma unroll
        for (int o=16;o>=1;o>>=1) s_lat += __shfl_xor_sync(0xffffffffu,s_lat,o);
        if (lane==0) misc[1+w] = s_lat;
        __syncthreads();
        if (tid==0){
            float t=0.f;
#pragma unroll
            for (int i=0;i<8;++i) t += misc[1+i];
            g_part[blockIdx.x]=t;
        }
        __syncthreads();
    }

    // ===== chain =============================================================
    chain_gemm(0, SACT_A, 0, SACT_B, b_e1, 0,0,0, tid, row0);            // emb1: A->B
    chain_gemm(1, SACT_B, 0, SACT_A, b_e2, 0,0,0, tid, row0);            // emb2: B->A
    chain_gemm(2, SACT_A, 0, SACT_B, b_c0, 0,0,0, tid, row0);            // c0:   A->B
    chain_gemm(3, SACT_B, 1, 0, b_c1, W_c2, b_c2, out_critic, tid, row0);// c1 -> critic
    chain_gemm(4, SACT_A, 0, SACT_B, b_a0, 0,0,0, tid, row0);            // a0:   A->B
    chain_gemm(5, SACT_B, 2, 0, b_a1, 0,0, out_probs, tid, row0);        // a1 -> softmax

    // ===== last-CTA vq_loss finalize ========================================
    __threadfence();
    if (tid==0){
        u32 p = atomicAdd(&g_ctr, 1u);
        misc[0] = (p==NCTA-1) ? 1.f : 0.f;
    }
    __syncthreads();
    if (misc[0] != 0.f){
        float s = 0.f;
        for (int i=tid; i<NCTA; i+=THREADS) s += g_part[i];
#pragma unroll
        for (int o=16;o>=1;o>>=1) s += __shfl_xor_sync(0xffffffffu,s,o);
        if (lane==0) misc[1+w] = s;
        __syncthreads();
        if (tid==0){
            float t=0.f;
#pragma unroll
            for (int i=0;i<8;++i) t += misc[1+i];
            out_vq[0] = (float)((double)t * (1.25/((double)NB*64.0)));
            g_ctr = 0;
        }
    }
}

// ---------------------------------------------------------------------------
extern "C" void kernel_launch(void* const* d_in, const int* in_sizes, int n_in,
                              void* d_out, int out_size)
{
    const float* x    = (const float*)d_in[0];
    const float* W_e0 = (const float*)d_in[1];  const float* b_e0 = (const float*)d_in[2];
    const float* W_e1 = (const float*)d_in[3];  const float* b_e1 = (const float*)d_in[4];
    const float* W_e2 = (const float*)d_in[5];  const float* b_e2 = (const float*)d_in[6];
    const float* W_p  = (const float*)d_in[7];  const float* b_p  = (const float*)d_in[8];
    const float* E    = (const float*)d_in[9];
    const float* W_a0 = (const float*)d_in[10]; const float* b_a0 = (const float*)d_in[11];
    const float* W_a1 = (const float*)d_in[12]; const float* b_a1 = (const float*)d_in[13];
    const float* W_c0 = (const float*)d_in[14]; const float* b_c0 = (const float*)d_in[15];
    const float* W_c1 = (const float*)d_in[16]; const float* b_c1 = (const float*)d_in[17];
    const float* W_c2 = (const float*)d_in[18]; const float* b_c2 = (const float*)d_in[19];

    float* o = (float*)d_out;
    const size_t P = (size_t)NB*128;
    float* out_probs  = o;
    float* out_critic = o + P;
    float* out_vq     = o + P + NB;
    float* out_idx    = o + P + NB + 1;

    static bool inited = false;
    if (!inited){
        cudaFuncSetAttribute(acsq_kernel,
                             cudaFuncAttributeMaxDynamicSharedMemorySize, SMEM_TOTAL);
        inited = true;
    }
    prep_kernel<<<896,256>>>(W_e0,W_e1,W_e2,W_c0,W_c1,W_a0,W_a1);
    acsq_kernel<<<NCTA,THREADS,SMEM_TOTAL>>>(
        x, W_p, b_e0, b_e1, b_e2, b_p, E, b_a0, b_a1, b_c0, b_c1, W_c2, b_c2,
        out_probs, out_critic, out_vq, out_idx);
}